// round 17
// baseline (speedup 1.0000x reference)
#include <cuda_runtime.h>
#include <cuda_fp16.h>
#include <cuda_bf16.h>

#define BB  4
#define CD  48
#define HW  16384
#define D1  384
#define OC4 1536

__device__ __half g_qkv0[(size_t)BB * OC4 * HW];   // after 1x1 conv (fp16)
__device__ __half g_qkv [(size_t)BB * OC4 * HW];   // after dw conv (fp16)
__device__ float g_red [BB * 3 * D1];
__device__ float g_L   [BB * D1];
__device__ float g_Spart[(size_t)BB * 8 * 64 * 2304];
__device__ float g_A   [(size_t)BB * 8 * 2304];

// K1: 1x1 conv 48->1536, HFMA2 over pixel pairs. grid(128,12,4), 256thr, dyn smem 36864
__global__ __launch_bounds__(256) void k1_conv1x1(const float* __restrict__ x,
                                                  const float* __restrict__ qw) {
    extern __shared__ char smc[];
    __half2* Wh = (__half2*)smc;                 // [48][128] dup weight pairs
    __half2* Xs = (__half2*)(smc + 48 * 128 * 4); // [48][64] pixel pairs
    int b = blockIdx.z, ot = blockIdx.y, pt = blockIdx.x, t = threadIdx.x;
    for (int idx = t; idx < 48 * 128; idx += 256) {
        int o = idx / 48, k = idx % 48;
        Wh[k * 128 + o] = __float2half2_rn(qw[(ot * 128 + o) * 48 + k]);
    }
    const float* xb = x + (size_t)b * CD * HW + pt * 128;
    for (int idx = t; idx < 48 * 64; idx += 256) {
        int k = idx / 64, pp = idx % 64;
        float2 v = ((const float2*)(xb + (size_t)k * HW))[pp];
        Xs[k * 64 + pp] = __floats2half2_rn(v.x, v.y);
    }
    __syncthreads();
    int tp = t & 15, ot8 = t >> 4;
    __half2 acc[8][4];
#pragma unroll
    for (int i = 0; i < 8; i++)
#pragma unroll
        for (int j = 0; j < 4; j++) acc[i][j] = __floats2half2_rn(0.f, 0.f);
    for (int k = 0; k < 48; k++) {
        __half2 xp[4];
#pragma unroll
        for (int j = 0; j < 4; j++) xp[j] = Xs[k * 64 + tp + 16 * j];
#pragma unroll
        for (int i = 0; i < 8; i++) {
            __half2 w2 = Wh[k * 128 + ot8 * 8 + i];
#pragma unroll
            for (int j = 0; j < 4; j++) acc[i][j] = __hfma2(xp[j], w2, acc[i][j]);
        }
    }
    __half* outb = g_qkv0 + ((size_t)b * OC4 + ot * 128) * HW + pt * 128;
#pragma unroll
    for (int i = 0; i < 8; i++) {
        __half2* orow = (__half2*)(outb + (size_t)(ot8 * 8 + i) * HW);
#pragma unroll
        for (int j = 0; j < 4; j++) orow[tp + 16 * j] = acc[i][j];
    }
}

// K2: grouped 3x3 conv, HFMA2 over oc pairs. grid(4,192,4), 256thr, dyn smem 70848
__global__ __launch_bounds__(256) void k2_dwconv(const float* __restrict__ dw) {
    extern __shared__ char smc[];
    __half*  sx = (__half*)smc;                      // [8][66][66] halo
    __half2* wp = (__half2*)(smc + 8 * 66 * 66 * 2); // [8 il][9 tap][4 oc-pair]
    int tileid = blockIdx.x, g = blockIdx.y, b = blockIdx.z, t = threadIdx.x;
    int ty0 = (tileid >> 1) * 64, tx0 = (tileid & 1) * 64;
    const __half* inb = g_qkv0 + ((size_t)b * OC4 + g * 8) * HW;
    for (int idx = t; idx < 8 * 66 * 66; idx += 256) {
        int ch = idx / (66 * 66), rem = idx % (66 * 66);
        int yy = rem / 66, xx = rem % 66;
        int gy = ty0 + yy - 1, gx = tx0 + xx - 1;
        __half v = __float2half(0.0f);
        if (gy >= 0 && gy < 128 && gx >= 0 && gx < 128) v = inb[(size_t)ch * HW + gy * 128 + gx];
        sx[idx] = v;
    }
    for (int idx = t; idx < 288; idx += 256) {
        int il = idx / 36, rem = idx % 36, tap = rem / 4, op = rem % 4;
        wp[idx] = __floats2half2_rn(dw[(g * 8 + 2 * op) * 72 + il * 9 + tap],
                                    dw[(g * 8 + 2 * op + 1) * 72 + il * 9 + tap]);
    }
    __syncthreads();
    __half* outb = g_qkv + ((size_t)b * OC4 + g * 8) * HW;
    for (int s0 = 0; s0 < 2; s0++) {
        int s = t + s0 * 256, sy = s >> 3, x0 = (s & 7) * 8;
        __half2 acc[8][4];   // [px][oc-pair]
#pragma unroll
        for (int px = 0; px < 8; px++)
#pragma unroll
            for (int op = 0; op < 4; op++) acc[px][op] = __floats2half2_rn(0.f, 0.f);
        for (int il = 0; il < 8; il++) {
            const __half* base = sx + il * 66 * 66;
#pragma unroll
            for (int ky = 0; ky < 3; ky++) {
                const __half* row = base + (sy + ky) * 66 + x0;
                __half2 d[10];
#pragma unroll
                for (int m = 0; m < 10; m++) d[m] = __half2half2(row[m]);
#pragma unroll
                for (int kx = 0; kx < 3; kx++) {
                    int tap = ky * 3 + kx;
                    __half2 w0 = wp[il * 36 + tap * 4 + 0], w1 = wp[il * 36 + tap * 4 + 1];
                    __half2 w2 = wp[il * 36 + tap * 4 + 2], w3 = wp[il * 36 + tap * 4 + 3];
#pragma unroll
                    for (int px = 0; px < 8; px++) {
                        __half2 v = d[px + kx];
                        acc[px][0] = __hfma2(v, w0, acc[px][0]);
                        acc[px][1] = __hfma2(v, w1, acc[px][1]);
                        acc[px][2] = __hfma2(v, w2, acc[px][2]);
                        acc[px][3] = __hfma2(v, w3, acc[px][3]);
                    }
                }
            }
        }
        int off = (ty0 + sy) * 128 + tx0 + x0;
#pragma unroll
        for (int op = 0; op < 4; op++) {
            __half2* oL = (__half2*)(outb + (size_t)(2 * op) * HW + off);
            __half2* oH = (__half2*)(outb + (size_t)(2 * op + 1) * HW + off);
#pragma unroll
            for (int pp = 0; pp < 4; pp++) {
                oL[pp] = __halves2half2(__low2half(acc[2 * pp][op]),  __low2half(acc[2 * pp + 1][op]));
                oH[pp] = __halves2half2(__high2half(acc[2 * pp][op]), __high2half(acc[2 * pp + 1][op]));
            }
        }
    }
}

// K3: q sumsq / k sumsq / l sum (half2 loads, fp32 accum). grid(384,3,4), 256thr
__global__ void k3_reduce() {
    int ch = blockIdx.x, type = blockIdx.y, b = blockIdx.z, t = threadIdx.x;
    int base_ch = (type == 0) ? ch : (type == 1) ? 384 + ch : 1152 + ch;
    const __half2* src = (const __half2*)(g_qkv + ((size_t)b * OC4 + base_ch) * HW);
    float s = 0.0f;
    for (int p = t; p < HW / 2; p += 256) {
        float2 v = __half22float2(src[p]);
        s += (type == 2) ? (v.x + v.y) : (v.x * v.x + v.y * v.y);
    }
    __shared__ float red[256];
    red[t] = s; __syncthreads();
    for (int off = 128; off > 0; off >>= 1) { if (t < off) red[t] += red[t + off]; __syncthreads(); }
    if (t == 0) g_red[(b * 3 + type) * D1 + ch] = red[0];
}

// K4: channel MLP -> L (swish). grid(4), 384thr
__global__ void k4_mlp(const float* __restrict__ fc1w, const float* __restrict__ fc1b,
                       const float* __restrict__ fc2w, const float* __restrict__ fc2b) {
    int b = blockIdx.x, t = threadIdx.x;
    __shared__ float avg[384], y1[24];
    avg[t] = g_red[(b * 3 + 2) * D1 + t] * (1.0f / 16384.0f);
    __syncthreads();
    if (t < 24) {
        float s = fc1b[t];
        for (int c = 0; c < 384; c++) s += fc1w[t * 384 + c] * avg[c];
        y1[t] = fmaxf(s, 0.0f);
    }
    __syncthreads();
    float s = fc2b[t];
    for (int j = 0; j < 24; j++) s += fc2w[t * 24 + j] * y1[j];
    g_L[b * D1 + t] = s / (1.0f + expf(-s));
}

// K5: raw q.k^T partials (half2 loads, fp32 accum). grid(64,32), 256thr, dyn smem 98688
__global__ __launch_bounds__(256) void k5_scores() {
    extern __shared__ float sm[];
    float* qs = sm;            // [48][257]
    float* ks = sm + 48 * 257;
    int ck = blockIdx.x, bh = blockIdx.y, b = bh >> 3, h = bh & 7;
    int p0 = ck * 256, t = threadIdx.x;
    const __half* qb = g_qkv + ((size_t)b * OC4 + h * 48) * HW + p0;
    const __half* kb = g_qkv + ((size_t)b * OC4 + 384 + h * 48) * HW + p0;
    for (int idx = t; idx < 48 * 128; idx += 256) {
        int c = idx >> 7, pp = idx & 127;
        float2 qv = __half22float2(((const __half2*)(qb + (size_t)c * HW))[pp]);
        float2 kv = __half22float2(((const __half2*)(kb + (size_t)c * HW))[pp]);
        qs[c * 257 + 2 * pp] = qv.x; qs[c * 257 + 2 * pp + 1] = qv.y;
        ks[c * 257 + 2 * pp] = kv.x; ks[c * 257 + 2 * pp + 1] = kv.y;
    }
    __syncthreads();
    int tc = t & 15, td = t >> 4;
    float acc[3][3];
#pragma unroll
    for (int i = 0; i < 3; i++)
#pragma unroll
        for (int j = 0; j < 3; j++) acc[i][j] = 0.0f;
    for (int p = 0; p < 256; p++) {
        float qv[3], kv[3];
#pragma unroll
        for (int i = 0; i < 3; i++) qv[i] = qs[(tc + 16 * i) * 257 + p];
#pragma unroll
        for (int j = 0; j < 3; j++) kv[j] = ks[(td + 16 * j) * 257 + p];
#pragma unroll
        for (int i = 0; i < 3; i++)
#pragma unroll
            for (int j = 0; j < 3; j++) acc[i][j] = fmaf(qv[i], kv[j], acc[i][j]);
    }
    float* outp = g_Spart + ((size_t)bh * 64 + ck) * 2304;
#pragma unroll
    for (int i = 0; i < 3; i++)
#pragma unroll
        for (int j = 0; j < 3; j++)
            outp[(tc + 16 * i) * 48 + td + 16 * j] = acc[i][j];
}

// K6: reduce partials, scale, softmax rows. grid(32), 256thr
__global__ void k6_softmax(const float* __restrict__ temp) {
    __shared__ float S[2304];
    __shared__ float iq[48], ik[48];
    int bh = blockIdx.x, b = bh >> 3, h = bh & 7, t = threadIdx.x;
    if (t < 48) iq[t] = 1.0f / fmaxf(sqrtf(g_red[(b * 3 + 0) * D1 + h * 48 + t]), 1e-12f);
    else if (t < 96) { int c = t - 48; ik[c] = 1.0f / fmaxf(sqrtf(g_red[(b * 3 + 1) * D1 + h * 48 + c]), 1e-12f); }
    __syncthreads();
    float tm = temp[h];
    for (int idx = t; idx < 2304; idx += 256) {
        float s = 0.0f;
        for (int k = 0; k < 64; k++) s += g_Spart[((size_t)bh * 64 + k) * 2304 + idx];
        S[idx] = s * iq[idx / 48] * ik[idx % 48] * tm;
    }
    __syncthreads();
    if (t < 48) {
        float m = -1e30f;
        for (int d = 0; d < 48; d++) m = fmaxf(m, S[t * 48 + d]);
        float sum = 0.0f;
        for (int d = 0; d < 48; d++) { float e = expf(S[t * 48 + d] - m); sum += e; S[t * 48 + d] = e; }
        float inv = 1.0f / sum;
        for (int d = 0; d < 48; d++) g_A[(size_t)bh * 2304 + t * 48 + d] = S[t * 48 + d] * inv;
    }
}

// K78: fused (attn@v + L) -> po1 projection -> + x. grid(128 pt, 4 b), 256thr, dyn smem 67584
__global__ __launch_bounds__(256) void k78_fused(const float* __restrict__ x,
                                                 const float* __restrict__ po1w,
                                                 float* __restrict__ out) {
    extern __shared__ float sm[];
    float* As  = sm;                  // [48 c][48 d] attention
    float* Wsm = sm + 2304;           // [48 cl][48 o] po1 slice for this head
    float* vs  = sm + 4608;           // [48 d][128 p] v tile
    float* ao  = sm + 4608 + 6144;    // [48 c][128 p] per-head attention output
    int pt = blockIdx.x, b = blockIdx.y, t = threadIdx.x;
    int tp = t & 15, tc = t >> 4;     // rows r = tc*3+i, cols p = tp+16j

    float accO[3][8];
#pragma unroll
    for (int i = 0; i < 3; i++)
#pragma unroll
        for (int j = 0; j < 8; j++) accO[i][j] = 0.0f;

    for (int h = 0; h < 8; h++) {
        int bh = b * 8 + h;
        for (int idx = t; idx < 2304; idx += 256) As[idx] = g_A[(size_t)bh * 2304 + idx];
        for (int idx = t; idx < 2304; idx += 256) {
            int cl = idx / 48, o = idx % 48;
            Wsm[cl * 48 + o] = po1w[o * 384 + h * 48 + cl];
        }
        const __half* vb = g_qkv + ((size_t)b * OC4 + 768 + h * 48) * HW + pt * 128;
        for (int idx = t; idx < 48 * 64; idx += 256) {
            int d = idx >> 6, pp = idx & 63;
            float2 v = __half22float2(((const __half2*)(vb + (size_t)d * HW))[pp]);
            vs[d * 128 + 2 * pp] = v.x; vs[d * 128 + 2 * pp + 1] = v.y;
        }
        __syncthreads();

        // stage 1: ao = A @ v  (+ L)
        float acc1[3][8];
#pragma unroll
        for (int i = 0; i < 3; i++)
#pragma unroll
            for (int j = 0; j < 8; j++) acc1[i][j] = 0.0f;
        for (int d = 0; d < 48; d++) {
            float av[3], vv[8];
#pragma unroll
            for (int i = 0; i < 3; i++) av[i] = As[(tc * 3 + i) * 48 + d];
#pragma unroll
            for (int j = 0; j < 8; j++) vv[j] = vs[d * 128 + tp + 16 * j];
#pragma unroll
            for (int i = 0; i < 3; i++)
#pragma unroll
                for (int j = 0; j < 8; j++) acc1[i][j] = fmaf(av[i], vv[j], acc1[i][j]);
        }
#pragma unroll
        for (int i = 0; i < 3; i++) {
            float Lv = g_L[b * D1 + h * 48 + tc * 3 + i];
#pragma unroll
            for (int j = 0; j < 8; j++)
                ao[(tc * 3 + i) * 128 + tp + 16 * j] = acc1[i][j] + Lv;
        }
        __syncthreads();

        // stage 2: accO += po1_h^T @ ao
        for (int cl = 0; cl < 48; cl++) {
            float w[3], vv[8];
#pragma unroll
            for (int i = 0; i < 3; i++) w[i] = Wsm[cl * 48 + tc * 3 + i];
#pragma unroll
            for (int j = 0; j < 8; j++) vv[j] = ao[cl * 128 + tp + 16 * j];
#pragma unroll
            for (int i = 0; i < 3; i++)
#pragma unroll
                for (int j = 0; j < 8; j++) accO[i][j] = fmaf(w[i], vv[j], accO[i][j]);
        }
        __syncthreads();
    }

    const float* xb = x + (size_t)b * CD * HW + pt * 128;
    float* ob = out + (size_t)b * CD * HW + pt * 128;
#pragma unroll
    for (int i = 0; i < 3; i++) {
        int o = tc * 3 + i;
#pragma unroll
        for (int j = 0; j < 8; j++) {
            int p = tp + 16 * j;
            ob[(size_t)o * HW + p] = accO[i][j] + xb[(size_t)o * HW + p];
        }
    }
}

extern "C" void kernel_launch(void* const* d_in, const int* in_sizes, int n_in,
                              void* d_out, int out_size) {
    const float* x    = (const float*)d_in[0];
    const float* qkvw = (const float*)d_in[1];
    const float* dww  = (const float*)d_in[2];
    const float* po1w = (const float*)d_in[3];
    const float* fc1w = (const float*)d_in[4];
    const float* fc1b = (const float*)d_in[5];
    const float* fc2w = (const float*)d_in[6];
    const float* fc2b = (const float*)d_in[7];
    const float* temp = (const float*)d_in[8];
    float* out = (float*)d_out;

    cudaFuncSetAttribute(k1_conv1x1, cudaFuncAttributeMaxDynamicSharedMemorySize, 36864);
    cudaFuncSetAttribute(k2_dwconv,  cudaFuncAttributeMaxDynamicSharedMemorySize, 70848);
    cudaFuncSetAttribute(k5_scores,  cudaFuncAttributeMaxDynamicSharedMemorySize, 98688);
    cudaFuncSetAttribute(k78_fused,  cudaFuncAttributeMaxDynamicSharedMemorySize, 67584);

    k1_conv1x1<<<dim3(128, 12, 4), 256, 36864>>>(x, qkvw);
    k2_dwconv <<<dim3(4, 192, 4), 256, 70848>>>(dww);
    k3_reduce <<<dim3(384, 3, 4), 256>>>();
    k4_mlp    <<<4, 384>>>(fc1w, fc1b, fc2w, fc2b);
    k5_scores <<<dim3(64, 32), 256, 98688>>>();
    k6_softmax<<<32, 256>>>(temp);
    k78_fused <<<dim3(128, 4), 256, 67584>>>(x, po1w, out);
}